// round 1
// baseline (speedup 1.0000x reference)
#include <cuda_runtime.h>
#include <math.h>

#define NN   50000
#define EE   800000
#define EP   850000   // EE + NN self loops
#define GG   512

// ---------------- scratch (static device globals; no allocation allowed) ----
__device__ float g_loop_sum[NN * 3];
__device__ float g_loop_attr[NN * 3];
__device__ int   g_cnt[NN];
__device__ int   g_rowptr[NN + 1];
__device__ int   g_cursor[NN];
__device__ int   g_srcs[EP];
__device__ int   g_eids[EP];
__device__ float g_xl1[NN * 128];
__device__ float g_xr1[NN * 128];
__device__ float g_h1[NN * 128];
__device__ float g_xl2[NN * 64];
__device__ float g_xr2[NN * 64];
__device__ float g_h2[NN * 64];
__device__ float g_pooled[GG * 64];
__device__ int   g_gcnt[GG];

// ---------------- zero scratch that accumulates ----------------------------
__global__ void k_zero() {
    int i = blockIdx.x * blockDim.x + threadIdx.x;
    if (i < NN * 3) g_loop_sum[i] = 0.f;
    if (i < NN)    { g_cnt[i] = 0; g_cursor[i] = 0; }
    if (i < GG * 64) g_pooled[i] = 0.f;
    if (i < GG)      g_gcnt[i] = 0;
}

// ---------------- in-degree + self-loop attr mean sums ---------------------
__global__ void k_degree(const int* __restrict__ ei, const float* __restrict__ ea) {
    int e = blockIdx.x * blockDim.x + threadIdx.x;
    if (e >= EE) return;
    int d = ei[EE + e];                 // dst = row 1 of edge_index
    atomicAdd(&g_cnt[d], 1);
    atomicAdd(&g_loop_sum[d * 3 + 0], ea[e * 3 + 0]);
    atomicAdd(&g_loop_sum[d * 3 + 1], ea[e * 3 + 1]);
    atomicAdd(&g_loop_sum[d * 3 + 2], ea[e * 3 + 2]);
}

__global__ void k_loopattr() {
    int v = blockIdx.x * blockDim.x + threadIdx.x;
    if (v >= NN) return;
    float c = fmaxf((float)g_cnt[v], 1.f);
    g_loop_attr[v * 3 + 0] = g_loop_sum[v * 3 + 0] / c;
    g_loop_attr[v * 3 + 1] = g_loop_sum[v * 3 + 1] / c;
    g_loop_attr[v * 3 + 2] = g_loop_sum[v * 3 + 2] / c;
}

// ---------------- exclusive scan of (deg+1) into rowptr (single block) -----
__global__ void k_scan() {
    __shared__ int ps[1024];
    const int CH = (NN + 1023) / 1024;
    int t = threadIdx.x;
    int base = t * CH;
    int s = 0;
    for (int i = 0; i < CH; i++) { int v = base + i; if (v < NN) s += g_cnt[v] + 1; }
    ps[t] = s;
    __syncthreads();
    for (int off = 1; off < 1024; off <<= 1) {
        int val = (t >= off) ? ps[t - off] : 0;
        __syncthreads();
        ps[t] += val;
        __syncthreads();
    }
    int run = (t > 0) ? ps[t - 1] : 0;
    for (int i = 0; i < CH; i++) {
        int v = base + i;
        if (v < NN) { g_rowptr[v] = run; run += g_cnt[v] + 1; }
    }
    if (t == 0) g_rowptr[NN] = ps[1023];
}

// ---------------- scatter edges into CSR-by-dst ----------------------------
__global__ void k_scatter(const int* __restrict__ ei) {
    int e = blockIdx.x * blockDim.x + threadIdx.x;
    if (e >= EP) return;
    int s, d;
    if (e < EE) { s = ei[e]; d = ei[EE + e]; }
    else        { s = d = e - EE; }
    int pos = g_rowptr[d] + atomicAdd(&g_cursor[d], 1);
    g_srcs[pos] = s;
    g_eids[pos] = e;
}

// ---------------- fp32 tiled GEMM: C[m][n] = sum_k A[m][k]*W[n][k] + b[n] --
// BM=64 BN=64 BK=16, 256 threads, 4x4 register tile
__global__ void sgemm_bias(const float* __restrict__ A, const float* __restrict__ W,
                           const float* __restrict__ bias, float* __restrict__ C,
                           int M, int K, int Ncol) {
    __shared__ float As[64][16];
    __shared__ float Bs[16][64];
    int tid = threadIdx.x;
    int bm = blockIdx.y * 64;
    int bn = blockIdx.x * 64;
    int tx = tid % 16, ty = tid / 16;
    int a_row = (tid * 4) / 16;
    int a_col = (tid * 4) % 16;
    float acc[4][4] = {};
    for (int k0 = 0; k0 < K; k0 += 16) {
        float4 av = make_float4(0.f, 0.f, 0.f, 0.f);
        int gr = bm + a_row;
        if (gr < M) av = *(const float4*)&A[gr * K + k0 + a_col];
        *(float4*)&As[a_row][a_col] = av;
        float4 wv = *(const float4*)&W[(bn + a_row) * K + k0 + a_col];
        Bs[a_col + 0][a_row] = wv.x;
        Bs[a_col + 1][a_row] = wv.y;
        Bs[a_col + 2][a_row] = wv.z;
        Bs[a_col + 3][a_row] = wv.w;
        __syncthreads();
#pragma unroll
        for (int k = 0; k < 16; ++k) {
            float rm[4], rn[4];
#pragma unroll
            for (int i = 0; i < 4; i++) rm[i] = As[ty * 4 + i][k];
            float4 b4 = *(float4*)&Bs[k][tx * 4];
            rn[0] = b4.x; rn[1] = b4.y; rn[2] = b4.z; rn[3] = b4.w;
#pragma unroll
            for (int i = 0; i < 4; i++)
#pragma unroll
                for (int j = 0; j < 4; j++) acc[i][j] += rm[i] * rn[j];
        }
        __syncthreads();
    }
#pragma unroll
    for (int i = 0; i < 4; i++) {
        int gr = bm + ty * 4 + i;
        if (gr >= M) continue;
#pragma unroll
        for (int j = 0; j < 4; j++) {
            int gc = bn + tx * 4 + j;
            C[gr * Ncol + gc] = acc[i][j] + bias[gc];
        }
    }
}

// ---------------- GATv2 layer 1: warp per node, online softmax, 4 heads ----
__global__ void k_gat1(const float* __restrict__ eattr,
                       const float* __restrict__ We, const float* __restrict__ att,
                       const float* __restrict__ bias) {
    int gw = (blockIdx.x * blockDim.x + threadIdx.x) >> 5;
    int lane = threadIdx.x & 31;
    if (gw >= NN) return;
    int v = gw;
    float a[4], w0[4], w1[4], w2[4], xrv[4];
#pragma unroll
    for (int k = 0; k < 4; k++) {
        int ch = k * 32 + lane;
        a[k] = att[ch];
        w0[k] = We[ch * 3 + 0];
        w1[k] = We[ch * 3 + 1];
        w2[k] = We[ch * 3 + 2];
        xrv[k] = g_xr1[v * 128 + ch];
    }
    float mx[4], den[4], acc[4];
#pragma unroll
    for (int k = 0; k < 4; k++) { mx[k] = -1e30f; den[k] = 0.f; acc[k] = 0.f; }
    int pend = g_rowptr[v + 1];
    for (int p = g_rowptr[v]; p < pend; ++p) {
        int s = g_srcs[p];
        int e = g_eids[p];
        const float* ea = (e < EE) ? (eattr + (long)e * 3) : (g_loop_attr + (long)(e - EE) * 3);
        float e0 = __ldg(ea), e1 = __ldg(ea + 1), e2 = __ldg(ea + 2);
        float sc[4], xlv[4];
#pragma unroll
        for (int k = 0; k < 4; k++) {
            xlv[k] = g_xl1[(long)s * 128 + k * 32 + lane];
            float m = xlv[k] + xrv[k] + w0[k] * e0 + w1[k] * e1 + w2[k] * e2;
            m = (m > 0.f) ? m : 0.2f * m;
            sc[k] = m * a[k];
        }
#pragma unroll
        for (int k = 0; k < 4; k++) {
#pragma unroll
            for (int off = 16; off > 0; off >>= 1)
                sc[k] += __shfl_xor_sync(0xffffffffu, sc[k], off);
        }
#pragma unroll
        for (int k = 0; k < 4; k++) {
            float nm = fmaxf(mx[k], sc[k]);
            float corr = __expf(mx[k] - nm);
            float pe = __expf(sc[k] - nm);
            den[k] = den[k] * corr + pe;
            acc[k] = acc[k] * corr + pe * xlv[k];
            mx[k] = nm;
        }
    }
#pragma unroll
    for (int k = 0; k < 4; k++) {
        int ch = k * 32 + lane;
        float o = acc[k] / den[k] + bias[ch];
        g_h1[(long)v * 128 + ch] = (o > 0.f) ? o : (__expf(o) - 1.f);
    }
}

// ---------------- GATv2 layer 2: warp per node, 1 head, 64 ch --------------
__global__ void k_gat2(const float* __restrict__ eattr,
                       const float* __restrict__ We, const float* __restrict__ att,
                       const float* __restrict__ bias) {
    int gw = (blockIdx.x * blockDim.x + threadIdx.x) >> 5;
    int lane = threadIdx.x & 31;
    if (gw >= NN) return;
    int v = gw;
    int c0 = lane, c1 = lane + 32;
    float aa = att[c0], ab = att[c1];
    float wa0 = We[c0 * 3 + 0], wa1 = We[c0 * 3 + 1], wa2 = We[c0 * 3 + 2];
    float wb0 = We[c1 * 3 + 0], wb1 = We[c1 * 3 + 1], wb2 = We[c1 * 3 + 2];
    float xra = g_xr2[v * 64 + c0], xrb = g_xr2[v * 64 + c1];
    float mx = -1e30f, den = 0.f, acca = 0.f, accb = 0.f;
    int pend = g_rowptr[v + 1];
    for (int p = g_rowptr[v]; p < pend; ++p) {
        int s = g_srcs[p];
        int e = g_eids[p];
        const float* ea = (e < EE) ? (eattr + (long)e * 3) : (g_loop_attr + (long)(e - EE) * 3);
        float e0 = __ldg(ea), e1 = __ldg(ea + 1), e2 = __ldg(ea + 2);
        float xla = g_xl2[(long)s * 64 + c0];
        float xlb = g_xl2[(long)s * 64 + c1];
        float ma = xla + xra + wa0 * e0 + wa1 * e1 + wa2 * e2;
        float mb = xlb + xrb + wb0 * e0 + wb1 * e1 + wb2 * e2;
        ma = (ma > 0.f) ? ma : 0.2f * ma;
        mb = (mb > 0.f) ? mb : 0.2f * mb;
        float sc = ma * aa + mb * ab;
#pragma unroll
        for (int off = 16; off > 0; off >>= 1)
            sc += __shfl_xor_sync(0xffffffffu, sc, off);
        float nm = fmaxf(mx, sc);
        float corr = __expf(mx - nm);
        float pe = __expf(sc - nm);
        den = den * corr + pe;
        acca = acca * corr + pe * xla;
        accb = accb * corr + pe * xlb;
        mx = nm;
    }
    float oa = acca / den + bias[c0];
    float ob = accb / den + bias[c1];
    g_h2[(long)v * 64 + c0] = (oa > 0.f) ? oa : (__expf(oa) - 1.f);
    g_h2[(long)v * 64 + c1] = (ob > 0.f) ? ob : (__expf(ob) - 1.f);
}

// ---------------- mean pooling -------------------------------------------
__global__ void k_pool(const int* __restrict__ batch) {
    int idx = blockIdx.x * blockDim.x + threadIdx.x;
    if (idx >= NN * 64) return;
    int v = idx >> 6;
    int c = idx & 63;
    int b = batch[v];
    atomicAdd(&g_pooled[b * 64 + c], g_h2[idx]);
    if (c == 0) atomicAdd(&g_gcnt[b], 1);
}

// ---------------- head MLP: block per graph --------------------------------
__global__ void k_head(const float* __restrict__ u,
                       const float* __restrict__ Wl, const float* __restrict__ bl,
                       const float* __restrict__ Wh, const float* __restrict__ bh,
                       float* __restrict__ out) {
    int g = blockIdx.x;
    __shared__ float pm[64];
    __shared__ float z[32];
    int t = threadIdx.x;   // 64 threads
    float c = fmaxf((float)g_gcnt[g], 1.f);
    pm[t] = g_pooled[g * 64 + t] / c;
    __syncthreads();
    if (t < 32) {
        float s = bl[t];
#pragma unroll
        for (int k = 0; k < 64; k++) s += pm[k] * Wl[t * 65 + k];
        s += u[g] * Wl[t * 65 + 64];
        z[t] = fmaxf(s, 0.f);
    }
    __syncthreads();
    if (t < 10) {
        float s = bh[t];
#pragma unroll
        for (int j = 0; j < 32; j++) s += z[j] * Wh[t * 32 + j];
        out[g * 10 + t] = s;
    }
}

// ---------------- launch ----------------------------------------------------
extern "C" void kernel_launch(void* const* d_in, const int* in_sizes, int n_in,
                              void* d_out, int out_size) {
    const float* x     = (const float*)d_in[0];
    const int*   ei    = (const int*)d_in[1];
    const float* ea    = (const float*)d_in[2];
    const int*   batch = (const int*)d_in[3];
    const float* u     = (const float*)d_in[4];
    const float* Wl1   = (const float*)d_in[5];
    const float* bl1   = (const float*)d_in[6];
    const float* Wr1   = (const float*)d_in[7];
    const float* br1   = (const float*)d_in[8];
    const float* We1   = (const float*)d_in[9];
    const float* att1  = (const float*)d_in[10];
    const float* b1    = (const float*)d_in[11];
    const float* Wl2   = (const float*)d_in[12];
    const float* bl2   = (const float*)d_in[13];
    const float* Wr2   = (const float*)d_in[14];
    const float* br2   = (const float*)d_in[15];
    const float* We2   = (const float*)d_in[16];
    const float* att2  = (const float*)d_in[17];
    const float* b2    = (const float*)d_in[18];
    const float* Wlin  = (const float*)d_in[19];
    const float* blin  = (const float*)d_in[20];
    const float* Wh    = (const float*)d_in[21];
    const float* bh    = (const float*)d_in[22];
    float* out = (float*)d_out;

    float *p_xl1, *p_xr1, *p_h1, *p_xl2, *p_xr2;
    cudaGetSymbolAddress((void**)&p_xl1, g_xl1);
    cudaGetSymbolAddress((void**)&p_xr1, g_xr1);
    cudaGetSymbolAddress((void**)&p_h1,  g_h1);
    cudaGetSymbolAddress((void**)&p_xl2, g_xl2);
    cudaGetSymbolAddress((void**)&p_xr2, g_xr2);

    k_zero<<<(NN * 3 + 255) / 256, 256>>>();
    k_degree<<<(EE + 255) / 256, 256>>>(ei, ea);
    k_loopattr<<<(NN + 255) / 256, 256>>>();
    k_scan<<<1, 1024>>>();
    k_scatter<<<(EP + 255) / 256, 256>>>(ei);

    dim3 g1(2, (NN + 63) / 64);
    sgemm_bias<<<g1, 256>>>(x, Wl1, bl1, p_xl1, NN, 128, 128);
    sgemm_bias<<<g1, 256>>>(x, Wr1, br1, p_xr1, NN, 128, 128);

    k_gat1<<<(NN + 7) / 8, 256>>>(ea, We1, att1, b1);

    dim3 g2(1, (NN + 63) / 64);
    sgemm_bias<<<g2, 256>>>(p_h1, Wl2, bl2, p_xl2, NN, 128, 64);
    sgemm_bias<<<g2, 256>>>(p_h1, Wr2, br2, p_xr2, NN, 128, 64);

    k_gat2<<<(NN + 7) / 8, 256>>>(ea, We2, att2, b2);

    k_pool<<<(NN * 64 + 255) / 256, 256>>>(batch);
    k_head<<<GG, 64>>>(u, Wlin, blin, Wh, bh, out);
}

// round 5
// speedup vs baseline: 1.1238x; 1.1238x over previous
#include <cuda_runtime.h>
#include <math.h>

#define NN   50000
#define EE   800000
#define EP   850000   // EE + NN self loops
#define GG   512

// ---------------- scratch (static device globals; no allocation allowed) ----
__device__ float g_loop_sum[NN * 3];
__device__ float g_loop_attr[NN * 3];
__device__ int   g_cnt[NN];
__device__ int   g_rowptr[NN + 1];
__device__ int   g_cursor[NN];
__device__ int   g_srcs[EP];
__device__ int   g_eids[EP];
__device__ float g_xl1[NN * 128];
__device__ float g_xr1[NN * 128];
__device__ float g_h1[NN * 128];
__device__ float g_xl2[NN * 64];
__device__ float g_xr2[NN * 64];
__device__ float g_h2[NN * 64];
__device__ float g_pooled[GG * 64];
__device__ int   g_gcnt[GG];

// ---------------- zero scratch that accumulates ----------------------------
__global__ void k_zero() {
    int i = blockIdx.x * blockDim.x + threadIdx.x;
    if (i < NN * 3) g_loop_sum[i] = 0.f;
    if (i < NN)    { g_cnt[i] = 0; g_cursor[i] = 0; }
    if (i < GG * 64) g_pooled[i] = 0.f;
    if (i < GG)      g_gcnt[i] = 0;
}

// ---------------- in-degree + self-loop attr mean sums ---------------------
__global__ void k_degree(const int* __restrict__ ei, const float* __restrict__ ea) {
    int e = blockIdx.x * blockDim.x + threadIdx.x;
    if (e >= EE) return;
    int d = ei[EE + e];                 // dst = row 1 of edge_index
    atomicAdd(&g_cnt[d], 1);
    atomicAdd(&g_loop_sum[d * 3 + 0], ea[e * 3 + 0]);
    atomicAdd(&g_loop_sum[d * 3 + 1], ea[e * 3 + 1]);
    atomicAdd(&g_loop_sum[d * 3 + 2], ea[e * 3 + 2]);
}

__global__ void k_loopattr() {
    int v = blockIdx.x * blockDim.x + threadIdx.x;
    if (v >= NN) return;
    float c = fmaxf((float)g_cnt[v], 1.f);
    g_loop_attr[v * 3 + 0] = g_loop_sum[v * 3 + 0] / c;
    g_loop_attr[v * 3 + 1] = g_loop_sum[v * 3 + 1] / c;
    g_loop_attr[v * 3 + 2] = g_loop_sum[v * 3 + 2] / c;
}

// ---------------- exclusive scan of (deg+1) into rowptr (single block) -----
// (R1-proven version; re-optimize only after GEMM is validated)
__global__ void k_scan() {
    __shared__ int ps[1024];
    const int CH = (NN + 1023) / 1024;
    int t = threadIdx.x;
    int base = t * CH;
    int s = 0;
    for (int i = 0; i < CH; i++) { int v = base + i; if (v < NN) s += g_cnt[v] + 1; }
    ps[t] = s;
    __syncthreads();
    for (int off = 1; off < 1024; off <<= 1) {
        int val = (t >= off) ? ps[t - off] : 0;
        __syncthreads();
        ps[t] += val;
        __syncthreads();
    }
    int run = (t > 0) ? ps[t - 1] : 0;
    for (int i = 0; i < CH; i++) {
        int v = base + i;
        if (v < NN) { g_rowptr[v] = run; run += g_cnt[v] + 1; }
    }
    if (t == 0) g_rowptr[NN] = ps[1023];
}

// ---------------- scatter edges into CSR-by-dst ----------------------------
__global__ void k_scatter(const int* __restrict__ ei) {
    int e = blockIdx.x * blockDim.x + threadIdx.x;
    if (e >= EP) return;
    int s, d;
    if (e < EE) { s = ei[e]; d = ei[EE + e]; }
    else        { s = d = e - EE; }
    int pos = g_rowptr[d] + atomicAdd(&g_cursor[d], 1);
    g_srcs[pos] = s;
    g_eids[pos] = e;
}

// ---------------- tf32 tensor-core GEMM (m16n8k4, static 36KB smem) --------
// C[m][n] = sum_k A[m][k] * W[n][k] + bias[n],  K = 128 fixed.
// Weight split into tf32 hi + lo (2-pass MMA) -> near-fp32 weight accuracy.
// BM=128, BN=64, BK=32 chunks, 256 threads (8 warps: 4 over M, 2 over N).
// blockIdx.z in {0,1} selects (W0,b0,C0) or (W1,b1,C1) -> fused xl/xr pair.

__device__ __forceinline__ unsigned f2tf32(float f) {
    unsigned r;
    asm("cvt.rna.tf32.f32 %0, %1;" : "=r"(r) : "f"(f));
    return r;
}

// m16n8k4 tf32 fragment layout (forced by counting; gid=lane>>2, tig=lane&3):
// A = {a0=(gid,tig), a1=(gid+8,tig)}, B = {b0=(k=tig, n=gid)},
// C = {c0=(gid,2tig), c1=(gid,2tig+1), c2=(gid+8,2tig), c3=(gid+8,2tig+1)}
__device__ __forceinline__ void mma_k4(float c[4], unsigned a0, unsigned a1, unsigned b0) {
    asm volatile(
        "mma.sync.aligned.m16n8k4.row.col.f32.tf32.tf32.f32 "
        "{%0,%1,%2,%3}, {%4,%5}, {%6}, {%0,%1,%2,%3};"
        : "+f"(c[0]), "+f"(c[1]), "+f"(c[2]), "+f"(c[3])
        : "r"(a0), "r"(a1), "r"(b0));
}

__global__ void gemm_tf32(const float* __restrict__ A,
                          const float* __restrict__ W0, const float* __restrict__ W1,
                          const float* __restrict__ bias0, const float* __restrict__ bias1,
                          float* __restrict__ C0, float* __restrict__ C1,
                          int M, int Ncol) {
    __shared__ unsigned Bh[64][36];
    __shared__ unsigned Bl[64][36];
    __shared__ unsigned As[128][36];

    const float* W    = blockIdx.z ? W1 : W0;
    const float* bias = blockIdx.z ? bias1 : bias0;
    float*       C    = blockIdx.z ? C1 : C0;

    int tid = threadIdx.x;
    int lane = tid & 31, warp = tid >> 5;
    int bm = blockIdx.y * 128;
    int bn = blockIdx.x * 64;
    int wm = (warp & 3) * 32;
    int wn = (warp >> 2) * 32;
    int lr = lane >> 2;       // groupID 0..7
    int lc = lane & 3;        // threadID_in_group 0..3

    float c[2][4][4] = {};

    for (int k0 = 0; k0 < 128; k0 += 32) {
        // load W chunk (64 rows x 32 k), split hi/lo: 512 float4s, 2 per thread
#pragma unroll
        for (int i = 0; i < 2; i++) {
            int idx = tid + i * 256;        // 0..511
            int n = idx >> 3;               // 0..63
            int c4 = (idx & 7) * 4;         // 0..28
            float4 wv = *(const float4*)&W[(size_t)(bn + n) * 128 + k0 + c4];
            float w[4] = {wv.x, wv.y, wv.z, wv.w};
#pragma unroll
            for (int j = 0; j < 4; j++) {
                unsigned hi = f2tf32(w[j]);
                float lo = w[j] - __uint_as_float(hi);
                Bh[n][c4 + j] = hi;
                Bl[n][c4 + j] = f2tf32(lo);
            }
        }
        // load A chunk (128 rows x 32 k): 1024 float4s, 4 per thread
#pragma unroll
        for (int i = 0; i < 4; i++) {
            int idx = tid + i * 256;        // 0..1023
            int r = idx >> 3;               // 0..127
            int c4 = (idx & 7) * 4;         // 0..28
            float4 av = make_float4(0.f, 0.f, 0.f, 0.f);
            if (bm + r < M) av = *(const float4*)&A[(size_t)(bm + r) * 128 + k0 + c4];
            As[r][c4 + 0] = f2tf32(av.x);
            As[r][c4 + 1] = f2tf32(av.y);
            As[r][c4 + 2] = f2tf32(av.z);
            As[r][c4 + 3] = f2tf32(av.w);
        }
        __syncthreads();

#pragma unroll
        for (int kk = 0; kk < 32; kk += 4) {
            unsigned a0[2], a1[2], bh[4], bl[4];
#pragma unroll
            for (int mt = 0; mt < 2; mt++) {
                int row = wm + mt * 16 + lr;
                a0[mt] = As[row][kk + lc];
                a1[mt] = As[row + 8][kk + lc];
            }
#pragma unroll
            for (int nt = 0; nt < 4; nt++) {
                int n = wn + nt * 8 + lr;
                bh[nt] = Bh[n][kk + lc];
                bl[nt] = Bl[n][kk + lc];
            }
#pragma unroll
            for (int mt = 0; mt < 2; mt++)
#pragma unroll
                for (int nt = 0; nt < 4; nt++) {
                    mma_k4(c[mt][nt], a0[mt], a1[mt], bh[nt]);
                    mma_k4(c[mt][nt], a0[mt], a1[mt], bl[nt]);
                }
        }
        __syncthreads();
    }

    // epilogue
#pragma unroll
    for (int mt = 0; mt < 2; mt++) {
#pragma unroll
        for (int nt = 0; nt < 4; nt++) {
            int r0 = bm + wm + mt * 16 + lr;
            int cc = bn + wn + nt * 8 + lc * 2;
            float b0v = bias[cc], b1v = bias[cc + 1];
            if (r0 < M) {
                C[(size_t)r0 * Ncol + cc]     = c[mt][nt][0] + b0v;
                C[(size_t)r0 * Ncol + cc + 1] = c[mt][nt][1] + b1v;
            }
            if (r0 + 8 < M) {
                C[(size_t)(r0 + 8) * Ncol + cc]     = c[mt][nt][2] + b0v;
                C[(size_t)(r0 + 8) * Ncol + cc + 1] = c[mt][nt][3] + b1v;
            }
        }
    }
}

// ---------------- GATv2 layer 1: warp per node, online softmax, 4 heads ----
__global__ void k_gat1(const float* __restrict__ eattr,
                       const float* __restrict__ We, const float* __restrict__ att,
                       const float* __restrict__ bias) {
    int gw = (blockIdx.x * blockDim.x + threadIdx.x) >> 5;
    int lane = threadIdx.x & 31;
    if (gw >= NN) return;
    int v = gw;
    float a[4], w0[4], w1[4], w2[4], xrv[4];
#pragma unroll
    for (int k = 0; k < 4; k++) {
        int ch = k * 32 + lane;
        a[k] = att[ch];
        w0[k] = We[ch * 3 + 0];
        w1[k] = We[ch * 3 + 1];
        w2[k] = We[ch * 3 + 2];
        xrv[k] = g_xr1[v * 128 + ch];
    }
    float mx[4], den[4], acc[4];
#pragma unroll
    for (int k = 0; k < 4; k++) { mx[k] = -1e30f; den[k] = 0.f; acc[k] = 0.f; }
    int pend = g_rowptr[v + 1];
    for (int p = g_rowptr[v]; p < pend; ++p) {
        int s = g_srcs[p];
        int e = g_eids[p];
        const float* ea = (e < EE) ? (eattr + (long)e * 3) : (g_loop_attr + (long)(e - EE) * 3);
        float e0 = __ldg(ea), e1 = __ldg(ea + 1), e2 = __ldg(ea + 2);
        float sc[4], xlv[4];
#pragma unroll
        for (int k = 0; k < 4; k++) {
            xlv[k] = g_xl1[(long)s * 128 + k * 32 + lane];
            float m = xlv[k] + xrv[k] + w0[k] * e0 + w1[k] * e1 + w2[k] * e2;
            m = (m > 0.f) ? m : 0.2f * m;
            sc[k] = m * a[k];
        }
#pragma unroll
        for (int k = 0; k < 4; k++) {
#pragma unroll
            for (int off = 16; off > 0; off >>= 1)
                sc[k] += __shfl_xor_sync(0xffffffffu, sc[k], off);
        }
#pragma unroll
        for (int k = 0; k < 4; k++) {
            float nm = fmaxf(mx[k], sc[k]);
            float corr = __expf(mx[k] - nm);
            float pe = __expf(sc[k] - nm);
            den[k] = den[k] * corr + pe;
            acc[k] = acc[k] * corr + pe * xlv[k];
            mx[k] = nm;
        }
    }
#pragma unroll
    for (int k = 0; k < 4; k++) {
        int ch = k * 32 + lane;
        float o = acc[k] / den[k] + bias[ch];
        g_h1[(long)v * 128 + ch] = (o > 0.f) ? o : (__expf(o) - 1.f);
    }
}

// ---------------- GATv2 layer 2: warp per node, 1 head, 64 ch --------------
__global__ void k_gat2(const float* __restrict__ eattr,
                       const float* __restrict__ We, const float* __restrict__ att,
                       const float* __restrict__ bias) {
    int gw = (blockIdx.x * blockDim.x + threadIdx.x) >> 5;
    int lane = threadIdx.x & 31;
    if (gw >= NN) return;
    int v = gw;
    int c0 = lane, c1 = lane + 32;
    float aa = att[c0], ab = att[c1];
    float wa0 = We[c0 * 3 + 0], wa1 = We[c0 * 3 + 1], wa2 = We[c0 * 3 + 2];
    float wb0 = We[c1 * 3 + 0], wb1 = We[c1 * 3 + 1], wb2 = We[c1 * 3 + 2];
    float xra = g_xr2[v * 64 + c0], xrb = g_xr2[v * 64 + c1];
    float mx = -1e30f, den = 0.f, acca = 0.f, accb = 0.f;
    int pend = g_rowptr[v + 1];
    for (int p = g_rowptr[v]; p < pend; ++p) {
        int s = g_srcs[p];
        int e = g_eids[p];
        const float* ea = (e < EE) ? (eattr + (long)e * 3) : (g_loop_attr + (long)(e - EE) * 3);
        float e0 = __ldg(ea), e1 = __ldg(ea + 1), e2 = __ldg(ea + 2);
        float xla = g_xl2[(long)s * 64 + c0];
        float xlb = g_xl2[(long)s * 64 + c1];
        float ma = xla + xra + wa0 * e0 + wa1 * e1 + wa2 * e2;
        float mb = xlb + xrb + wb0 * e0 + wb1 * e1 + wb2 * e2;
        ma = (ma > 0.f) ? ma : 0.2f * ma;
        mb = (mb > 0.f) ? mb : 0.2f * mb;
        float sc = ma * aa + mb * ab;
#pragma unroll
        for (int off = 16; off > 0; off >>= 1)
            sc += __shfl_xor_sync(0xffffffffu, sc, off);
        float nm = fmaxf(mx, sc);
        float corr = __expf(mx - nm);
        float pe = __expf(sc - nm);
        den = den * corr + pe;
        acca = acca * corr + pe * xla;
        accb = accb * corr + pe * xlb;
        mx = nm;
    }
    float oa = acca / den + bias[c0];
    float ob = accb / den + bias[c1];
    g_h2[(long)v * 64 + c0] = (oa > 0.f) ? oa : (__expf(oa) - 1.f);
    g_h2[(long)v * 64 + c1] = (ob > 0.f) ? ob : (__expf(ob) - 1.f);
}

// ---------------- mean pooling -------------------------------------------
__global__ void k_pool(const int* __restrict__ batch) {
    int idx = blockIdx.x * blockDim.x + threadIdx.x;
    if (idx >= NN * 64) return;
    int v = idx >> 6;
    int c = idx & 63;
    int b = batch[v];
    atomicAdd(&g_pooled[b * 64 + c], g_h2[idx]);
    if (c == 0) atomicAdd(&g_gcnt[b], 1);
}

// ---------------- head MLP: block per graph --------------------------------
__global__ void k_head(const float* __restrict__ u,
                       const float* __restrict__ Wl, const float* __restrict__ bl,
                       const float* __restrict__ Wh, const float* __restrict__ bh,
                       float* __restrict__ out) {
    int g = blockIdx.x;
    __shared__ float pm[64];
    __shared__ float z[32];
    int t = threadIdx.x;   // 64 threads
    float c = fmaxf((float)g_gcnt[g], 1.f);
    pm[t] = g_pooled[g * 64 + t] / c;
    __syncthreads();
    if (t < 32) {
        float s = bl[t];
#pragma unroll
        for (int k = 0; k < 64; k++) s += pm[k] * Wl[t * 65 + k];
        s += u[g] * Wl[t * 65 + 64];
        z[t] = fmaxf(s, 0.f);
    }
    __syncthreads();
    if (t < 10) {
        float s = bh[t];
#pragma unroll
        for (int j = 0; j < 32; j++) s += z[j] * Wh[t * 32 + j];
        out[g * 10 + t] = s;
    }
}

// ---------------- launch ----------------------------------------------------
extern "C" void kernel_launch(void* const* d_in, const int* in_sizes, int n_in,
                              void* d_out, int out_size) {
    const float* x     = (const float*)d_in[0];
    const int*   ei    = (const int*)d_in[1];
    const float* ea    = (const float*)d_in[2];
    const int*   batch = (const int*)d_in[3];
    const float* u     = (const float*)d_in[4];
    const float* Wl1   = (const float*)d_in[5];
    const float* bl1   = (const float*)d_in[6];
    const float* Wr1   = (const float*)d_in[7];
    const float* br1   = (const float*)d_in[8];
    const float* We1   = (const float*)d_in[9];
    const float* att1  = (const float*)d_in[10];
    const float* b1    = (const float*)d_in[11];
    const float* Wl2   = (const float*)d_in[12];
    const float* bl2   = (const float*)d_in[13];
    const float* Wr2   = (const float*)d_in[14];
    const float* br2   = (const float*)d_in[15];
    const float* We2   = (const float*)d_in[16];
    const float* att2  = (const float*)d_in[17];
    const float* b2    = (const float*)d_in[18];
    const float* Wlin  = (const float*)d_in[19];
    const float* blin  = (const float*)d_in[20];
    const float* Wh    = (const float*)d_in[21];
    const float* bh    = (const float*)d_in[22];
    float* out = (float*)d_out;

    float *p_xl1, *p_xr1, *p_h1, *p_xl2, *p_xr2;
    cudaGetSymbolAddress((void**)&p_xl1, g_xl1);
    cudaGetSymbolAddress((void**)&p_xr1, g_xr1);
    cudaGetSymbolAddress((void**)&p_h1,  g_h1);
    cudaGetSymbolAddress((void**)&p_xl2, g_xl2);
    cudaGetSymbolAddress((void**)&p_xr2, g_xr2);

    k_zero<<<(NN * 3 + 255) / 256, 256>>>();
    k_degree<<<(EE + 255) / 256, 256>>>(ei, ea);
    k_loopattr<<<(NN + 255) / 256, 256>>>();
    k_scan<<<1, 1024>>>();
    k_scatter<<<(EP + 255) / 256, 256>>>(ei);

    dim3 g1(2, (NN + 127) / 128, 2);
    gemm_tf32<<<g1, 256>>>(x, Wl1, Wr1, bl1, br1, p_xl1, p_xr1, NN, 128);

    k_gat1<<<(NN + 7) / 8, 256>>>(ea, We1, att1, b1);

    dim3 g2(1, (NN + 127) / 128, 2);
    gemm_tf32<<<g2, 256>>>(p_h1, Wl2, Wr2, bl2, br2, p_xl2, p_xr2, NN, 64);

    k_gat2<<<(NN + 7) / 8, 256>>>(ea, We2, att2, b2);

    k_pool<<<(NN * 64 + 255) / 256, 256>>>(batch);
    k_head<<<GG, 64>>>(u, Wlin, blin, Wh, bh, out);
}

// round 7
// speedup vs baseline: 1.3039x; 1.1602x over previous
#include <cuda_runtime.h>
#include <math.h>

#define NN   50000
#define EE   800000
#define EP   850000   // EE + NN self loops
#define GG   512

// ---------------- scratch (static device globals; no allocation allowed) ----
__device__ float g_loop_sum[NN * 3];
__device__ float g_loop_attr[NN * 3];
__device__ int   g_cnt[NN];
__device__ int   g_rowptr[NN + 1];
__device__ int   g_cursor[NN];
__device__ int   g_srcs[EP];
__device__ int   g_eids[EP];
__device__ float g_xl1[NN * 128];
__device__ float g_xr1[NN * 128];
__device__ float g_h1[NN * 128];
__device__ float g_xl2[NN * 64];
__device__ float g_xr2[NN * 64];
__device__ float g_h2[NN * 64];
__device__ float g_pooled[GG * 64];
__device__ int   g_gcnt[GG];
__device__ int   g_bsum[64];
__device__ int   g_boff[64];

// ---------------- zero scratch that accumulates ----------------------------
__global__ void k_zero() {
    int i = blockIdx.x * blockDim.x + threadIdx.x;
    if (i < NN * 3) g_loop_sum[i] = 0.f;
    if (i < NN)    { g_cnt[i] = 0; g_cursor[i] = 0; }
    if (i < GG * 64) g_pooled[i] = 0.f;
    if (i < GG)      g_gcnt[i] = 0;
}

// ---------------- in-degree + self-loop attr mean sums ---------------------
__global__ void k_degree(const int* __restrict__ ei, const float* __restrict__ ea) {
    int e = blockIdx.x * blockDim.x + threadIdx.x;
    if (e >= EE) return;
    int d = ei[EE + e];                 // dst = row 1 of edge_index
    atomicAdd(&g_cnt[d], 1);
    atomicAdd(&g_loop_sum[d * 3 + 0], ea[e * 3 + 0]);
    atomicAdd(&g_loop_sum[d * 3 + 1], ea[e * 3 + 1]);
    atomicAdd(&g_loop_sum[d * 3 + 2], ea[e * 3 + 2]);
}

__global__ void k_loopattr() {
    int v = blockIdx.x * blockDim.x + threadIdx.x;
    if (v >= NN) return;
    float c = fmaxf((float)g_cnt[v], 1.f);
    g_loop_attr[v * 3 + 0] = g_loop_sum[v * 3 + 0] / c;
    g_loop_attr[v * 3 + 1] = g_loop_sum[v * 3 + 1] / c;
    g_loop_attr[v * 3 + 2] = g_loop_sum[v * 3 + 2] / c;
}

// ---------------- multi-block exclusive scan of (deg+1) --------------------
// 64 blocks x 256 threads x 4 elems covers NN=50000
__global__ void k_scan1() {
    __shared__ int red[256];
    int t = threadIdx.x, b = blockIdx.x;
    int g = b * 256 + t;
    int s = 0;
#pragma unroll
    for (int i = 0; i < 4; i++) {
        int v = g * 4 + i;
        if (v < NN) s += g_cnt[v] + 1;
    }
    red[t] = s;
    __syncthreads();
    for (int off = 128; off > 0; off >>= 1) {
        if (t < off) red[t] += red[t + off];
        __syncthreads();
    }
    if (t == 0) g_bsum[b] = red[0];
}

__global__ void k_scan2() {
    if (threadIdx.x == 0) {
        int r = 0;
        for (int b = 0; b < 64; b++) { g_boff[b] = r; r += g_bsum[b]; }
    }
}

__global__ void k_scan3() {
    __shared__ int wsum[8];
    int t = threadIdx.x, b = blockIdx.x;
    int lane = t & 31, warp = t >> 5;
    int g = b * 256 + t;
    int vals[4];
    int tot = 0;
#pragma unroll
    for (int i = 0; i < 4; i++) {
        int v = g * 4 + i;
        vals[i] = (v < NN) ? g_cnt[v] + 1 : 0;
        tot += vals[i];
    }
    int inc = tot;
#pragma unroll
    for (int off = 1; off < 32; off <<= 1) {
        int n = __shfl_up_sync(0xffffffffu, inc, off);
        if (lane >= off) inc += n;
    }
    if (lane == 31) wsum[warp] = inc;
    __syncthreads();
    if (t == 0) {
        int r = 0;
        for (int w = 0; w < 8; w++) { int x = wsum[w]; wsum[w] = r; r += x; }
    }
    __syncthreads();
    int run = g_boff[b] + wsum[warp] + inc - tot;  // exclusive prefix of this thread
#pragma unroll
    for (int i = 0; i < 4; i++) {
        int v = g * 4 + i;
        if (v < NN) {
            g_rowptr[v] = run;
            run += vals[i];
            if (v == NN - 1) g_rowptr[NN] = run;
        }
    }
}

// ---------------- scatter edges into CSR-by-dst ----------------------------
__global__ void k_scatter(const int* __restrict__ ei) {
    int e = blockIdx.x * blockDim.x + threadIdx.x;
    if (e >= EP) return;
    int s, d;
    if (e < EE) { s = ei[e]; d = ei[EE + e]; }
    else        { s = d = e - EE; }
    int pos = g_rowptr[d] + atomicAdd(&g_cursor[d], 1);
    g_srcs[pos] = s;
    g_eids[pos] = e;
}

// ---------------- tf32 tensor-core GEMM (m16n8k4, static 28KB smem) --------
// C[m][n] = sum_k A[m][k] * W[n][k] + bias[n],  K = 128 fixed.
// Single tf32 rounding on both operands (validated headroom: A-only gave 1.7e-5).
// BM=128, BN=64, BK=32 chunks, 256 threads (8 warps: 4 over M, 2 over N).
// blockIdx.z in {0,1} selects (W0,b0,C0) or (W1,b1,C1) -> fused xl/xr pair.

__device__ __forceinline__ unsigned f2tf32(float f) {
    unsigned r;
    asm("cvt.rna.tf32.f32 %0, %1;" : "=r"(r) : "f"(f));
    return r;
}

// m16n8k4 tf32 fragment layout (forced by counting; gid=lane>>2, tig=lane&3):
// A = {a0=(gid,tig), a1=(gid+8,tig)}, B = {b0=(k=tig, n=gid)},
// C = {c0=(gid,2tig), c1=(gid,2tig+1), c2=(gid+8,2tig), c3=(gid+8,2tig+1)}
__device__ __forceinline__ void mma_k4(float c[4], unsigned a0, unsigned a1, unsigned b0) {
    asm volatile(
        "mma.sync.aligned.m16n8k4.row.col.f32.tf32.tf32.f32 "
        "{%0,%1,%2,%3}, {%4,%5}, {%6}, {%0,%1,%2,%3};"
        : "+f"(c[0]), "+f"(c[1]), "+f"(c[2]), "+f"(c[3])
        : "r"(a0), "r"(a1), "r"(b0));
}

__global__ void gemm_tf32(const float* __restrict__ A,
                          const float* __restrict__ W0, const float* __restrict__ W1,
                          const float* __restrict__ bias0, const float* __restrict__ bias1,
                          float* __restrict__ C0, float* __restrict__ C1,
                          int M, int Ncol) {
    __shared__ unsigned Bh[64][36];
    __shared__ unsigned As[128][36];

    const float* W    = blockIdx.z ? W1 : W0;
    const float* bias = blockIdx.z ? bias1 : bias0;
    float*       C    = blockIdx.z ? C1 : C0;

    int tid = threadIdx.x;
    int lane = tid & 31, warp = tid >> 5;
    int bm = blockIdx.y * 128;
    int bn = blockIdx.x * 64;
    int wm = (warp & 3) * 32;
    int wn = (warp >> 2) * 32;
    int lr = lane >> 2;       // groupID 0..7
    int lc = lane & 3;        // threadID_in_group 0..3

    float c[2][4][4] = {};

    for (int k0 = 0; k0 < 128; k0 += 32) {
        // load W chunk (64 rows x 32 k): 512 float4s, 2 per thread
#pragma unroll
        for (int i = 0; i < 2; i++) {
            int idx = tid + i * 256;        // 0..511
            int n = idx >> 3;               // 0..63
            int c4 = (idx & 7) * 4;         // 0..28
            float4 wv = *(const float4*)&W[(size_t)(bn + n) * 128 + k0 + c4];
            Bh[n][c4 + 0] = f2tf32(wv.x);
            Bh[n][c4 + 1] = f2tf32(wv.y);
            Bh[n][c4 + 2] = f2tf32(wv.z);
            Bh[n][c4 + 3] = f2tf32(wv.w);
        }
        // load A chunk (128 rows x 32 k): 1024 float4s, 4 per thread
#pragma unroll
        for (int i = 0; i < 4; i++) {
            int idx = tid + i * 256;        // 0..1023
            int r = idx >> 3;               // 0..127
            int c4 = (idx & 7) * 4;         // 0..28
            float4 av = make_float4(0.f, 0.f, 0.f, 0.f);
            if (bm + r < M) av = *(const float4*)&A[(size_t)(bm + r) * 128 + k0 + c4];
            As[r][c4 + 0] = f2tf32(av.x);
            As[r][c4 + 1] = f2tf32(av.y);
            As[r][c4 + 2] = f2tf32(av.z);
            As[r][c4 + 3] = f2tf32(av.w);
        }
        __syncthreads();

#pragma unroll
        for (int kk = 0; kk < 32; kk += 4) {
            unsigned a0[2], a1[2], bh[4];
#pragma unroll
            for (int mt = 0; mt < 2; mt++) {
                int row = wm + mt * 16 + lr;
                a0[mt] = As[row][kk + lc];
                a1[mt] = As[row + 8][kk + lc];
            }
#pragma unroll
            for (int nt = 0; nt < 4; nt++) {
                int n = wn + nt * 8 + lr;
                bh[nt] = Bh[n][kk + lc];
            }
#pragma unroll
            for (int mt = 0; mt < 2; mt++)
#pragma unroll
                for (int nt = 0; nt < 4; nt++)
                    mma_k4(c[mt][nt], a0[mt], a1[mt], bh[nt]);
        }
        __syncthreads();
    }

    // epilogue
#pragma unroll
    for (int mt = 0; mt < 2; mt++) {
#pragma unroll
        for (int nt = 0; nt < 4; nt++) {
            int r0 = bm + wm + mt * 16 + lr;
            int cc = bn + wn + nt * 8 + lc * 2;
            float b0v = bias[cc], b1v = bias[cc + 1];
            if (r0 < M) {
                C[(size_t)r0 * Ncol + cc]     = c[mt][nt][0] + b0v;
                C[(size_t)r0 * Ncol + cc + 1] = c[mt][nt][1] + b1v;
            }
            if (r0 + 8 < M) {
                C[(size_t)(r0 + 8) * Ncol + cc]     = c[mt][nt][2] + b0v;
                C[(size_t)(r0 + 8) * Ncol + cc + 1] = c[mt][nt][3] + b1v;
            }
        }
    }
}

// ---------------- GATv2 layer 1: warp per node, online softmax, 4 heads ----
__global__ void k_gat1(const float* __restrict__ eattr,
                       const float* __restrict__ We, const float* __restrict__ att,
                       const float* __restrict__ bias) {
    int gw = (blockIdx.x * blockDim.x + threadIdx.x) >> 5;
    int lane = threadIdx.x & 31;
    if (gw >= NN) return;
    int v = gw;
    float a[4], w0[4], w1[4], w2[4], xrv[4];
#pragma unroll
    for (int k = 0; k < 4; k++) {
        int ch = k * 32 + lane;
        a[k] = att[ch];
        w0[k] = We[ch * 3 + 0];
        w1[k] = We[ch * 3 + 1];
        w2[k] = We[ch * 3 + 2];
        xrv[k] = g_xr1[v * 128 + ch];
    }
    float mx[4], den[4], acc[4];
#pragma unroll
    for (int k = 0; k < 4; k++) { mx[k] = -1e30f; den[k] = 0.f; acc[k] = 0.f; }
    int pend = g_rowptr[v + 1];
    for (int p = g_rowptr[v]; p < pend; ++p) {
        int s = g_srcs[p];
        int e = g_eids[p];
        const float* ea = (e < EE) ? (eattr + (long)e * 3) : (g_loop_attr + (long)(e - EE) * 3);
        float e0 = __ldg(ea), e1 = __ldg(ea + 1), e2 = __ldg(ea + 2);
        float sc[4], xlv[4];
#pragma unroll
        for (int k = 0; k < 4; k++) {
            xlv[k] = g_xl1[(long)s * 128 + k * 32 + lane];
            float m = xlv[k] + xrv[k] + w0[k] * e0 + w1[k] * e1 + w2[k] * e2;
            m = (m > 0.f) ? m : 0.2f * m;
            sc[k] = m * a[k];
        }
#pragma unroll
        for (int k = 0; k < 4; k++) {
#pragma unroll
            for (int off = 16; off > 0; off >>= 1)
                sc[k] += __shfl_xor_sync(0xffffffffu, sc[k], off);
        }
#pragma unroll
        for (int k = 0; k < 4; k++) {
            float nm = fmaxf(mx[k], sc[k]);
            float corr = __expf(mx[k] - nm);
            float pe = __expf(sc[k] - nm);
            den[k] = den[k] * corr + pe;
            acc[k] = acc[k] * corr + pe * xlv[k];
            mx[k] = nm;
        }
    }
#pragma unroll
    for (int k = 0; k < 4; k++) {
        int ch = k * 32 + lane;
        float o = acc[k] / den[k] + bias[ch];
        g_h1[(long)v * 128 + ch] = (o > 0.f) ? o : (__expf(o) - 1.f);
    }
}

// ---------------- GATv2 layer 2: warp per node, 1 head, 64 ch --------------
__global__ void k_gat2(const float* __restrict__ eattr,
                       const float* __restrict__ We, const float* __restrict__ att,
                       const float* __restrict__ bias) {
    int gw = (blockIdx.x * blockDim.x + threadIdx.x) >> 5;
    int lane = threadIdx.x & 31;
    if (gw >= NN) return;
    int v = gw;
    int c0 = lane, c1 = lane + 32;
    float aa = att[c0], ab = att[c1];
    float wa0 = We[c0 * 3 + 0], wa1 = We[c0 * 3 + 1], wa2 = We[c0 * 3 + 2];
    float wb0 = We[c1 * 3 + 0], wb1 = We[c1 * 3 + 1], wb2 = We[c1 * 3 + 2];
    float xra = g_xr2[v * 64 + c0], xrb = g_xr2[v * 64 + c1];
    float mx = -1e30f, den = 0.f, acca = 0.f, accb = 0.f;
    int pend = g_rowptr[v + 1];
    for (int p = g_rowptr[v]; p < pend; ++p) {
        int s = g_srcs[p];
        int e = g_eids[p];
        const float* ea = (e < EE) ? (eattr + (long)e * 3) : (g_loop_attr + (long)(e - EE) * 3);
        float e0 = __ldg(ea), e1 = __ldg(ea + 1), e2 = __ldg(ea + 2);
        float xla = g_xl2[(long)s * 64 + c0];
        float xlb = g_xl2[(long)s * 64 + c1];
        float ma = xla + xra + wa0 * e0 + wa1 * e1 + wa2 * e2;
        float mb = xlb + xrb + wb0 * e0 + wb1 * e1 + wb2 * e2;
        ma = (ma > 0.f) ? ma : 0.2f * ma;
        mb = (mb > 0.f) ? mb : 0.2f * mb;
        float sc = ma * aa + mb * ab;
#pragma unroll
        for (int off = 16; off > 0; off >>= 1)
            sc += __shfl_xor_sync(0xffffffffu, sc, off);
        float nm = fmaxf(mx, sc);
        float corr = __expf(mx - nm);
        float pe = __expf(sc - nm);
        den = den * corr + pe;
        acca = acca * corr + pe * xla;
        accb = accb * corr + pe * xlb;
        mx = nm;
    }
    float oa = acca / den + bias[c0];
    float ob = accb / den + bias[c1];
    g_h2[(long)v * 64 + c0] = (oa > 0.f) ? oa : (__expf(oa) - 1.f);
    g_h2[(long)v * 64 + c1] = (ob > 0.f) ? ob : (__expf(ob) - 1.f);
}

// ---------------- mean pooling -------------------------------------------
__global__ void k_pool(const int* __restrict__ batch) {
    int idx = blockIdx.x * blockDim.x + threadIdx.x;
    if (idx >= NN * 64) return;
    int v = idx >> 6;
    int c = idx & 63;
    int b = batch[v];
    atomicAdd(&g_pooled[b * 64 + c], g_h2[idx]);
    if (c == 0) atomicAdd(&g_gcnt[b], 1);
}

// ---------------- head MLP: block per graph --------------------------------
__global__ void k_head(const float* __restrict__ u,
                       const float* __restrict__ Wl, const float* __restrict__ bl,
                       const float* __restrict__ Wh, const float* __restrict__ bh,
                       float* __restrict__ out) {
    int g = blockIdx.x;
    __shared__ float pm[64];
    __shared__ float z[32];
    int t = threadIdx.x;   // 64 threads
    float c = fmaxf((float)g_gcnt[g], 1.f);
    pm[t] = g_pooled[g * 64 + t] / c;
    __syncthreads();
    if (t < 32) {
        float s = bl[t];
#pragma unroll
        for (int k = 0; k < 64; k++) s += pm[k] * Wl[t * 65 + k];
        s += u[g] * Wl[t * 65 + 64];
        z[t] = fmaxf(s, 0.f);
    }
    __syncthreads();
    if (t < 10) {
        float s = bh[t];
#pragma unroll
        for (int j = 0; j < 32; j++) s += z[j] * Wh[t * 32 + j];
        out[g * 10 + t] = s;
    }
}

// ---------------- launch ----------------------------------------------------
extern "C" void kernel_launch(void* const* d_in, const int* in_sizes, int n_in,
                              void* d_out, int out_size) {
    const float* x     = (const float*)d_in[0];
    const int*   ei    = (const int*)d_in[1];
    const float* ea    = (const float*)d_in[2];
    const int*   batch = (const int*)d_in[3];
    const float* u     = (const float*)d_in[4];
    const float* Wl1   = (const float*)d_in[5];
    const float* bl1   = (const float*)d_in[6];
    const float* Wr1   = (const float*)d_in[7];
    const float* br1   = (const float*)d_in[8];
    const float* We1   = (const float*)d_in[9];
    const float* att1  = (const float*)d_in[10];
    const float* b1    = (const float*)d_in[11];
    const float* Wl2   = (const float*)d_in[12];
    const float* bl2   = (const float*)d_in[13];
    const float* Wr2   = (const float*)d_in[14];
    const float* br2   = (const float*)d_in[15];
    const float* We2   = (const float*)d_in[16];
    const float* att2  = (const float*)d_in[17];
    const float* b2    = (const float*)d_in[18];
    const float* Wlin  = (const float*)d_in[19];
    const float* blin  = (const float*)d_in[20];
    const float* Wh    = (const float*)d_in[21];
    const float* bh    = (const float*)d_in[22];
    float* out = (float*)d_out;

    float *p_xl1, *p_xr1, *p_h1, *p_xl2, *p_xr2;
    cudaGetSymbolAddress((void**)&p_xl1, g_xl1);
    cudaGetSymbolAddress((void**)&p_xr1, g_xr1);
    cudaGetSymbolAddress((void**)&p_h1,  g_h1);
    cudaGetSymbolAddress((void**)&p_xl2, g_xl2);
    cudaGetSymbolAddress((void**)&p_xr2, g_xr2);

    k_zero<<<(NN * 3 + 255) / 256, 256>>>();
    k_degree<<<(EE + 255) / 256, 256>>>(ei, ea);
    k_loopattr<<<(NN + 255) / 256, 256>>>();
    k_scan1<<<64, 256>>>();
    k_scan2<<<1, 32>>>();
    k_scan3<<<64, 256>>>();
    k_scatter<<<(EP + 255) / 256, 256>>>(ei);

    dim3 g1(2, (NN + 127) / 128, 2);
    gemm_tf32<<<g1, 256>>>(x, Wl1, Wr1, bl1, br1, p_xl1, p_xr1, NN, 128);

    k_gat1<<<(NN + 7) / 8, 256>>>(ea, We1, att1, b1);

    dim3 g2(1, (NN + 127) / 128, 2);
    gemm_tf32<<<g2, 256>>>(p_h1, Wl2, Wr2, bl2, br2, p_xl2, p_xr2, NN, 64);

    k_gat2<<<(NN + 7) / 8, 256>>>(ea, We2, att2, b2);

    k_pool<<<(NN * 64 + 255) / 256, 256>>>(batch);
    k_head<<<GG, 64>>>(u, Wlin, blin, Wh, bh, out);
}

// round 8
// speedup vs baseline: 1.3685x; 1.0495x over previous
#include <cuda_runtime.h>
#include <math.h>

#define NN   50000
#define EE   800000
#define GG   512

// ---------------- scratch (static device globals; no allocation allowed) ----
__device__ int    g_cnt[NN];
__device__ int    g_rowptr[NN + 1];
__device__ int    g_cursor[NN];
__device__ float4 g_edge[EE];          // {ea0, ea1, ea2, bitcast(src)} in CSR-by-dst order
__device__ float  g_xl1[NN * 128];
__device__ float  g_xr1[NN * 128];
__device__ float  g_h1[NN * 128];
__device__ float  g_xl2[NN * 64];
__device__ float  g_xr2[NN * 64];
__device__ float  g_pooled[GG * 64];
__device__ int    g_gcnt[GG];
__device__ int    g_bsum[64];
__device__ int    g_boff[64];

// ---------------- zero scratch that accumulates ----------------------------
__global__ void k_zero() {
    int i = blockIdx.x * blockDim.x + threadIdx.x;
    if (i < NN)    { g_cnt[i] = 0; g_cursor[i] = 0; }
    if (i < GG * 64) g_pooled[i] = 0.f;
    if (i < GG)      g_gcnt[i] = 0;
}

// ---------------- in-degree (int atomics only) -----------------------------
__global__ void k_degree(const int* __restrict__ ei) {
    int e = blockIdx.x * blockDim.x + threadIdx.x;
    if (e >= EE) return;
    atomicAdd(&g_cnt[ei[EE + e]], 1);
}

// ---------------- multi-block exclusive scan of deg ------------------------
// 64 blocks x 256 threads x 4 elems covers NN=50000
__global__ void k_scan1() {
    __shared__ int red[256];
    int t = threadIdx.x, b = blockIdx.x;
    int g = b * 256 + t;
    int s = 0;
#pragma unroll
    for (int i = 0; i < 4; i++) {
        int v = g * 4 + i;
        if (v < NN) s += g_cnt[v];
    }
    red[t] = s;
    __syncthreads();
    for (int off = 128; off > 0; off >>= 1) {
        if (t < off) red[t] += red[t + off];
        __syncthreads();
    }
    if (t == 0) g_bsum[b] = red[0];
}

__global__ void k_scan2() {
    if (threadIdx.x == 0) {
        int r = 0;
        for (int b = 0; b < 64; b++) { g_boff[b] = r; r += g_bsum[b]; }
    }
}

__global__ void k_scan3() {
    __shared__ int wsum[8];
    int t = threadIdx.x, b = blockIdx.x;
    int lane = t & 31, warp = t >> 5;
    int g = b * 256 + t;
    int vals[4];
    int tot = 0;
#pragma unroll
    for (int i = 0; i < 4; i++) {
        int v = g * 4 + i;
        vals[i] = (v < NN) ? g_cnt[v] : 0;
        tot += vals[i];
    }
    int inc = tot;
#pragma unroll
    for (int off = 1; off < 32; off <<= 1) {
        int n = __shfl_up_sync(0xffffffffu, inc, off);
        if (lane >= off) inc += n;
    }
    if (lane == 31) wsum[warp] = inc;
    __syncthreads();
    if (t == 0) {
        int r = 0;
        for (int w = 0; w < 8; w++) { int x = wsum[w]; wsum[w] = r; r += x; }
    }
    __syncthreads();
    int run = g_boff[b] + wsum[warp] + inc - tot;  // exclusive prefix of this thread
#pragma unroll
    for (int i = 0; i < 4; i++) {
        int v = g * 4 + i;
        if (v < NN) {
            g_rowptr[v] = run;
            run += vals[i];
            if (v == NN - 1) g_rowptr[NN] = run;
        }
    }
}

// ---------------- scatter edges (+attrs) into CSR-by-dst -------------------
__global__ void k_scatter(const int* __restrict__ ei, const float* __restrict__ ea) {
    int e = blockIdx.x * blockDim.x + threadIdx.x;
    if (e >= EE) return;
    int s = ei[e], d = ei[EE + e];
    int pos = g_rowptr[d] + atomicAdd(&g_cursor[d], 1);
    float4 q;
    q.x = ea[e * 3 + 0];
    q.y = ea[e * 3 + 1];
    q.z = ea[e * 3 + 2];
    q.w = __int_as_float(s);
    g_edge[pos] = q;
}

// ---------------- tf32 tensor-core GEMM (m16n8k4, static 28KB smem) --------
// C[m][n] = sum_k A[m][k] * W[n][k] + bias[n],  K = 128 fixed.
// BM=128, BN=64, BK=32 chunks, 256 threads (8 warps: 4 over M, 2 over N).
// blockIdx.z in {0,1} selects (W0,b0,C0) or (W1,b1,C1) -> fused xl/xr pair.

__device__ __forceinline__ unsigned f2tf32(float f) {
    unsigned r;
    asm("cvt.rna.tf32.f32 %0, %1;" : "=r"(r) : "f"(f));
    return r;
}

__device__ __forceinline__ void mma_k4(float c[4], unsigned a0, unsigned a1, unsigned b0) {
    asm volatile(
        "mma.sync.aligned.m16n8k4.row.col.f32.tf32.tf32.f32 "
        "{%0,%1,%2,%3}, {%4,%5}, {%6}, {%0,%1,%2,%3};"
        : "+f"(c[0]), "+f"(c[1]), "+f"(c[2]), "+f"(c[3])
        : "r"(a0), "r"(a1), "r"(b0));
}

__global__ void gemm_tf32(const float* __restrict__ A,
                          const float* __restrict__ W0, const float* __restrict__ W1,
                          const float* __restrict__ bias0, const float* __restrict__ bias1,
                          float* __restrict__ C0, float* __restrict__ C1,
                          int M, int Ncol) {
    __shared__ unsigned Bh[64][36];
    __shared__ unsigned As[128][36];

    const float* W    = blockIdx.z ? W1 : W0;
    const float* bias = blockIdx.z ? bias1 : bias0;
    float*       C    = blockIdx.z ? C1 : C0;

    int tid = threadIdx.x;
    int lane = tid & 31, warp = tid >> 5;
    int bm = blockIdx.y * 128;
    int bn = blockIdx.x * 64;
    int wm = (warp & 3) * 32;
    int wn = (warp >> 2) * 32;
    int lr = lane >> 2;       // groupID 0..7
    int lc = lane & 3;        // threadID_in_group 0..3

    float c[2][4][4] = {};

    for (int k0 = 0; k0 < 128; k0 += 32) {
#pragma unroll
        for (int i = 0; i < 2; i++) {
            int idx = tid + i * 256;
            int n = idx >> 3;
            int c4 = (idx & 7) * 4;
            float4 wv = *(const float4*)&W[(size_t)(bn + n) * 128 + k0 + c4];
            Bh[n][c4 + 0] = f2tf32(wv.x);
            Bh[n][c4 + 1] = f2tf32(wv.y);
            Bh[n][c4 + 2] = f2tf32(wv.z);
            Bh[n][c4 + 3] = f2tf32(wv.w);
        }
#pragma unroll
        for (int i = 0; i < 4; i++) {
            int idx = tid + i * 256;
            int r = idx >> 3;
            int c4 = (idx & 7) * 4;
            float4 av = make_float4(0.f, 0.f, 0.f, 0.f);
            if (bm + r < M) av = *(const float4*)&A[(size_t)(bm + r) * 128 + k0 + c4];
            As[r][c4 + 0] = f2tf32(av.x);
            As[r][c4 + 1] = f2tf32(av.y);
            As[r][c4 + 2] = f2tf32(av.z);
            As[r][c4 + 3] = f2tf32(av.w);
        }
        __syncthreads();

#pragma unroll
        for (int kk = 0; kk < 32; kk += 4) {
            unsigned a0[2], a1[2], bh[4];
#pragma unroll
            for (int mt = 0; mt < 2; mt++) {
                int row = wm + mt * 16 + lr;
                a0[mt] = As[row][kk + lc];
                a1[mt] = As[row + 8][kk + lc];
            }
#pragma unroll
            for (int nt = 0; nt < 4; nt++) {
                int n = wn + nt * 8 + lr;
                bh[nt] = Bh[n][kk + lc];
            }
#pragma unroll
            for (int mt = 0; mt < 2; mt++)
#pragma unroll
                for (int nt = 0; nt < 4; nt++)
                    mma_k4(c[mt][nt], a0[mt], a1[mt], bh[nt]);
        }
        __syncthreads();
    }

#pragma unroll
    for (int mt = 0; mt < 2; mt++) {
#pragma unroll
        for (int nt = 0; nt < 4; nt++) {
            int r0 = bm + wm + mt * 16 + lr;
            int cc = bn + wn + nt * 8 + lc * 2;
            float b0v = bias[cc], b1v = bias[cc + 1];
            if (r0 < M) {
                C[(size_t)r0 * Ncol + cc]     = c[mt][nt][0] + b0v;
                C[(size_t)r0 * Ncol + cc + 1] = c[mt][nt][1] + b1v;
            }
            if (r0 + 8 < M) {
                C[(size_t)(r0 + 8) * Ncol + cc]     = c[mt][nt][2] + b0v;
                C[(size_t)(r0 + 8) * Ncol + cc + 1] = c[mt][nt][3] + b1v;
            }
        }
    }
}

// ---------------- GATv2 layer 1: warp/node, online softmax, inline selfloop -
__global__ void k_gat1(const float* __restrict__ We, const float* __restrict__ att,
                       const float* __restrict__ bias) {
    int gw = (blockIdx.x * blockDim.x + threadIdx.x) >> 5;
    int lane = threadIdx.x & 31;
    if (gw >= NN) return;
    int v = gw;
    float a[4], w0[4], w1[4], w2[4], xrv[4];
#pragma unroll
    for (int k = 0; k < 4; k++) {
        int ch = k * 32 + lane;
        a[k] = att[ch];
        w0[k] = We[ch * 3 + 0];
        w1[k] = We[ch * 3 + 1];
        w2[k] = We[ch * 3 + 2];
        xrv[k] = g_xr1[v * 128 + ch];
    }
    float mx[4], den[4], acc[4];
#pragma unroll
    for (int k = 0; k < 4; k++) { mx[k] = -1e30f; den[k] = 0.f; acc[k] = 0.f; }
    int pbeg = g_rowptr[v], pend = g_rowptr[v + 1];
    float se0 = 0.f, se1 = 0.f, se2 = 0.f;
    for (int p = pbeg; p < pend; ++p) {
        float4 q = g_edge[p];
        int s = __float_as_int(q.w);
        se0 += q.x; se1 += q.y; se2 += q.z;
        float sc[4], xlv[4];
#pragma unroll
        for (int k = 0; k < 4; k++) {
            xlv[k] = g_xl1[(long)s * 128 + k * 32 + lane];
            float m = xlv[k] + xrv[k] + w0[k] * q.x + w1[k] * q.y + w2[k] * q.z;
            m = (m > 0.f) ? m : 0.2f * m;
            sc[k] = m * a[k];
        }
#pragma unroll
        for (int k = 0; k < 4; k++) {
#pragma unroll
            for (int off = 16; off > 0; off >>= 1)
                sc[k] += __shfl_xor_sync(0xffffffffu, sc[k], off);
        }
#pragma unroll
        for (int k = 0; k < 4; k++) {
            float nm = fmaxf(mx[k], sc[k]);
            float corr = __expf(mx[k] - nm);
            float pe = __expf(sc[k] - nm);
            den[k] = den[k] * corr + pe;
            acc[k] = acc[k] * corr + pe * xlv[k];
            mx[k] = nm;
        }
    }
    // self-loop: attr = mean of incoming real-edge attrs, src = v
    {
        float cinv = 1.f / fmaxf((float)(pend - pbeg), 1.f);
        float e0 = se0 * cinv, e1 = se1 * cinv, e2 = se2 * cinv;
        float sc[4], xlv[4];
#pragma unroll
        for (int k = 0; k < 4; k++) {
            xlv[k] = g_xl1[(long)v * 128 + k * 32 + lane];
            float m = xlv[k] + xrv[k] + w0[k] * e0 + w1[k] * e1 + w2[k] * e2;
            m = (m > 0.f) ? m : 0.2f * m;
            sc[k] = m * a[k];
        }
#pragma unroll
        for (int k = 0; k < 4; k++) {
#pragma unroll
            for (int off = 16; off > 0; off >>= 1)
                sc[k] += __shfl_xor_sync(0xffffffffu, sc[k], off);
        }
#pragma unroll
        for (int k = 0; k < 4; k++) {
            float nm = fmaxf(mx[k], sc[k]);
            float corr = __expf(mx[k] - nm);
            float pe = __expf(sc[k] - nm);
            den[k] = den[k] * corr + pe;
            acc[k] = acc[k] * corr + pe * xlv[k];
            mx[k] = nm;
        }
    }
#pragma unroll
    for (int k = 0; k < 4; k++) {
        int ch = k * 32 + lane;
        float o = acc[k] / den[k] + bias[ch];
        g_h1[(long)v * 128 + ch] = (o > 0.f) ? o : (__expf(o) - 1.f);
    }
}

// ---------------- GATv2 layer 2 + fused mean pooling -----------------------
__global__ void k_gat2(const float* __restrict__ We, const float* __restrict__ att,
                       const float* __restrict__ bias, const int* __restrict__ batch) {
    int gw = (blockIdx.x * blockDim.x + threadIdx.x) >> 5;
    int lane = threadIdx.x & 31;
    if (gw >= NN) return;
    int v = gw;
    int c0 = lane, c1 = lane + 32;
    float aa = att[c0], ab = att[c1];
    float wa0 = We[c0 * 3 + 0], wa1 = We[c0 * 3 + 1], wa2 = We[c0 * 3 + 2];
    float wb0 = We[c1 * 3 + 0], wb1 = We[c1 * 3 + 1], wb2 = We[c1 * 3 + 2];
    float xra = g_xr2[v * 64 + c0], xrb = g_xr2[v * 64 + c1];
    float mx = -1e30f, den = 0.f, acca = 0.f, accb = 0.f;
    int pbeg = g_rowptr[v], pend = g_rowptr[v + 1];
    float se0 = 0.f, se1 = 0.f, se2 = 0.f;
    for (int p = pbeg; p < pend; ++p) {
        float4 q = g_edge[p];
        int s = __float_as_int(q.w);
        se0 += q.x; se1 += q.y; se2 += q.z;
        float xla = g_xl2[(long)s * 64 + c0];
        float xlb = g_xl2[(long)s * 64 + c1];
        float ma = xla + xra + wa0 * q.x + wa1 * q.y + wa2 * q.z;
        float mb = xlb + xrb + wb0 * q.x + wb1 * q.y + wb2 * q.z;
        ma = (ma > 0.f) ? ma : 0.2f * ma;
        mb = (mb > 0.f) ? mb : 0.2f * mb;
        float sc = ma * aa + mb * ab;
#pragma unroll
        for (int off = 16; off > 0; off >>= 1)
            sc += __shfl_xor_sync(0xffffffffu, sc, off);
        float nm = fmaxf(mx, sc);
        float corr = __expf(mx - nm);
        float pe = __expf(sc - nm);
        den = den * corr + pe;
        acca = acca * corr + pe * xla;
        accb = accb * corr + pe * xlb;
        mx = nm;
    }
    // self-loop
    {
        float cinv = 1.f / fmaxf((float)(pend - pbeg), 1.f);
        float e0 = se0 * cinv, e1 = se1 * cinv, e2 = se2 * cinv;
        float xla = g_xl2[(long)v * 64 + c0];
        float xlb = g_xl2[(long)v * 64 + c1];
        float ma = xla + xra + wa0 * e0 + wa1 * e1 + wa2 * e2;
        float mb = xlb + xrb + wb0 * e0 + wb1 * e1 + wb2 * e2;
        ma = (ma > 0.f) ? ma : 0.2f * ma;
        mb = (mb > 0.f) ? mb : 0.2f * mb;
        float sc = ma * aa + mb * ab;
#pragma unroll
        for (int off = 16; off > 0; off >>= 1)
            sc += __shfl_xor_sync(0xffffffffu, sc, off);
        float nm = fmaxf(mx, sc);
        float corr = __expf(mx - nm);
        float pe = __expf(sc - nm);
        den = den * corr + pe;
        acca = acca * corr + pe * xla;
        accb = accb * corr + pe * xlb;
        mx = nm;
    }
    float oa = acca / den + bias[c0];
    float ob = accb / den + bias[c1];
    oa = (oa > 0.f) ? oa : (__expf(oa) - 1.f);
    ob = (ob > 0.f) ? ob : (__expf(ob) - 1.f);
    int b = batch[v];
    atomicAdd(&g_pooled[b * 64 + c0], oa);
    atomicAdd(&g_pooled[b * 64 + c1], ob);
    if (lane == 0) atomicAdd(&g_gcnt[b], 1);
}

// ---------------- head MLP: block per graph --------------------------------
__global__ void k_head(const float* __restrict__ u,
                       const float* __restrict__ Wl, const float* __restrict__ bl,
                       const float* __restrict__ Wh, const float* __restrict__ bh,
                       float* __restrict__ out) {
    int g = blockIdx.x;
    __shared__ float pm[64];
    __shared__ float z[32];
    int t = threadIdx.x;   // 64 threads
    float c = fmaxf((float)g_gcnt[g], 1.f);
    pm[t] = g_pooled[g * 64 + t] / c;
    __syncthreads();
    if (t < 32) {
        float s = bl[t];
#pragma unroll
        for (int k = 0; k < 64; k++) s += pm[k] * Wl[t * 65 + k];
        s += u[g] * Wl[t * 65 + 64];
        z[t] = fmaxf(s, 0.f);
    }
    __syncthreads();
    if (t < 10) {
        float s = bh[t];
#pragma unroll
        for (int j = 0; j < 32; j++) s += z[j] * Wh[t * 32 + j];
        out[g * 10 + t] = s;
    }
}

// ---------------- launch ----------------------------------------------------
extern "C" void kernel_launch(void* const* d_in, const int* in_sizes, int n_in,
                              void* d_out, int out_size) {
    const float* x     = (const float*)d_in[0];
    const int*   ei    = (const int*)d_in[1];
    const float* ea    = (const float*)d_in[2];
    const int*   batch = (const int*)d_in[3];
    const float* u     = (const float*)d_in[4];
    const float* Wl1   = (const float*)d_in[5];
    const float* bl1   = (const float*)d_in[6];
    const float* Wr1   = (const float*)d_in[7];
    const float* br1   = (const float*)d_in[8];
    const float* We1   = (const float*)d_in[9];
    const float* att1  = (const float*)d_in[10];
    const float* b1    = (const float*)d_in[11];
    const float* Wl2   = (const float*)d_in[12];
    const float* bl2   = (const float*)d_in[13];
    const float* Wr2   = (const float*)d_in[14];
    const float* br2   = (const float*)d_in[15];
    const float* We2   = (const float*)d_in[16];
    const float* att2  = (const float*)d_in[17];
    const float* b2    = (const float*)d_in[18];
    const float* Wlin  = (const float*)d_in[19];
    const float* blin  = (const float*)d_in[20];
    const float* Wh    = (const float*)d_in[21];
    const float* bh    = (const float*)d_in[22];
    float* out = (float*)d_out;

    float *p_xl1, *p_xr1, *p_h1, *p_xl2, *p_xr2;
    cudaGetSymbolAddress((void**)&p_xl1, g_xl1);
    cudaGetSymbolAddress((void**)&p_xr1, g_xr1);
    cudaGetSymbolAddress((void**)&p_h1,  g_h1);
    cudaGetSymbolAddress((void**)&p_xl2, g_xl2);
    cudaGetSymbolAddress((void**)&p_xr2, g_xr2);

    k_zero<<<(NN + 255) / 256, 256>>>();
    k_degree<<<(EE + 255) / 256, 256>>>(ei);
    k_scan1<<<64, 256>>>();
    k_scan2<<<1, 32>>>();
    k_scan3<<<64, 256>>>();
    k_scatter<<<(EE + 255) / 256, 256>>>(ei, ea);

    dim3 g1(2, (NN + 127) / 128, 2);
    gemm_tf32<<<g1, 256>>>(x, Wl1, Wr1, bl1, br1, p_xl1, p_xr1, NN, 128);

    k_gat1<<<(NN + 7) / 8, 256>>>(We1, att1, b1);

    dim3 g2(1, (NN + 127) / 128, 2);
    gemm_tf32<<<g2, 256>>>(p_h1, Wl2, Wr2, bl2, br2, p_xl2, p_xr2, NN, 64);

    k_gat2<<<(NN + 7) / 8, 256>>>(We2, att2, b2, batch);

    k_head<<<GG, 64>>>(u, Wlin, blin, Wh, bh, out);
}

// round 10
// speedup vs baseline: 1.6858x; 1.2319x over previous
#include <cuda_runtime.h>
#include <math.h>

#define NN   50000
#define EE   800000
#define GG   512

// ---------------- scratch (static device globals; no allocation allowed) ----
__device__ int    g_cnt[NN];
__device__ int    g_rowptr[NN + 1];
__device__ int    g_cursor[NN];
__device__ float4 g_edge[EE];          // {ea0, ea1, ea2, bitcast(src)} CSR-by-dst
__device__ float  g_xl1[NN * 128];
__device__ float  g_xr1[NN * 128];
__device__ float  g_h1[NN * 128];
__device__ float  g_xl2[NN * 64];
__device__ float  g_xr2[NN * 64];
__device__ float  g_pooled[GG * 64];
__device__ int    g_gcnt[GG];
__device__ int    g_bsum[64];

// ---------------- zero scratch that accumulates ----------------------------
// MUST cover NN threads (g_cnt), NN > GG*64 so all arrays are covered.
__global__ void k_zero() {
    int i = blockIdx.x * blockDim.x + threadIdx.x;
    if (i < NN)      g_cnt[i] = 0;
    if (i < GG * 64) g_pooled[i] = 0.f;
    if (i < GG)      g_gcnt[i] = 0;
}

// ---------------- in-degree (int atomics only) -----------------------------
__global__ void k_degree(const int* __restrict__ ei) {
    int e = blockIdx.x * blockDim.x + threadIdx.x;
    if (e >= EE) return;
    atomicAdd(&g_cnt[ei[EE + e]], 1);
}

// ---------------- 2-phase multi-block exclusive scan of deg ----------------
// 64 blocks x 256 threads x 4 elems covers NN=50000
__global__ void k_scan1() {
    __shared__ int red[256];
    int t = threadIdx.x, b = blockIdx.x;
    int g = b * 256 + t;
    int s = 0;
#pragma unroll
    for (int i = 0; i < 4; i++) {
        int v = g * 4 + i;
        if (v < NN) s += g_cnt[v];
    }
    red[t] = s;
    __syncthreads();
    for (int off = 128; off > 0; off >>= 1) {
        if (t < off) red[t] += red[t + off];
        __syncthreads();
    }
    if (t == 0) g_bsum[b] = red[0];
}

__global__ void k_scan3() {
    __shared__ int wsum[8];
    __shared__ int boff_s;
    int t = threadIdx.x, b = blockIdx.x;
    int lane = t & 31, warp = t >> 5;
    if (t == 0) {
        int r = 0;
        for (int i = 0; i < b; i++) r += g_bsum[i];
        boff_s = r;
    }
    int g = b * 256 + t;
    int vals[4];
    int tot = 0;
#pragma unroll
    for (int i = 0; i < 4; i++) {
        int v = g * 4 + i;
        vals[i] = (v < NN) ? g_cnt[v] : 0;
        tot += vals[i];
    }
    int inc = tot;
#pragma unroll
    for (int off = 1; off < 32; off <<= 1) {
        int n = __shfl_up_sync(0xffffffffu, inc, off);
        if (lane >= off) inc += n;
    }
    if (lane == 31) wsum[warp] = inc;
    __syncthreads();
    if (t == 0) {
        int r = 0;
        for (int w = 0; w < 8; w++) { int x = wsum[w]; wsum[w] = r; r += x; }
    }
    __syncthreads();
    int run = boff_s + wsum[warp] + inc - tot;  // exclusive prefix
#pragma unroll
    for (int i = 0; i < 4; i++) {
        int v = g * 4 + i;
        if (v < NN) {
            g_rowptr[v] = run;
            g_cursor[v] = run;       // scatter bumps this directly
            run += vals[i];
            if (v == NN - 1) g_rowptr[NN] = run;
        }
    }
}

// ---------------- scatter edges (+attrs) into CSR-by-dst -------------------
__global__ void k_scatter(const int* __restrict__ ei, const float* __restrict__ ea) {
    int e = blockIdx.x * blockDim.x + threadIdx.x;
    if (e >= EE) return;
    int s = ei[e], d = ei[EE + e];
    int pos = atomicAdd(&g_cursor[d], 1);
    float4 q;
    q.x = ea[e * 3 + 0];
    q.y = ea[e * 3 + 1];
    q.z = ea[e * 3 + 2];
    q.w = __int_as_float(s);
    g_edge[pos] = q;
}

// ---------------- tf32 tensor-core GEMM (m16n8k4, static 28KB smem) --------
__device__ __forceinline__ unsigned f2tf32(float f) {
    unsigned r;
    asm("cvt.rna.tf32.f32 %0, %1;" : "=r"(r) : "f"(f));
    return r;
}

__device__ __forceinline__ void mma_k4(float c[4], unsigned a0, unsigned a1, unsigned b0) {
    asm volatile(
        "mma.sync.aligned.m16n8k4.row.col.f32.tf32.tf32.f32 "
        "{%0,%1,%2,%3}, {%4,%5}, {%6}, {%0,%1,%2,%3};"
        : "+f"(c[0]), "+f"(c[1]), "+f"(c[2]), "+f"(c[3])
        : "r"(a0), "r"(a1), "r"(b0));
}

__global__ void gemm_tf32(const float* __restrict__ A,
                          const float* __restrict__ W0, const float* __restrict__ W1,
                          const float* __restrict__ bias0, const float* __restrict__ bias1,
                          float* __restrict__ C0, float* __restrict__ C1,
                          int M, int Ncol) {
    __shared__ unsigned Bh[64][36];
    __shared__ unsigned As[128][36];

    const float* W    = blockIdx.z ? W1 : W0;
    const float* bias = blockIdx.z ? bias1 : bias0;
    float*       C    = blockIdx.z ? C1 : C0;

    int tid = threadIdx.x;
    int lane = tid & 31, warp = tid >> 5;
    int bm = blockIdx.y * 128;
    int bn = blockIdx.x * 64;
    int wm = (warp & 3) * 32;
    int wn = (warp >> 2) * 32;
    int lr = lane >> 2;
    int lc = lane & 3;

    float c[2][4][4] = {};

    for (int k0 = 0; k0 < 128; k0 += 32) {
#pragma unroll
        for (int i = 0; i < 2; i++) {
            int idx = tid + i * 256;
            int n = idx >> 3;
            int c4 = (idx & 7) * 4;
            float4 wv = *(const float4*)&W[(size_t)(bn + n) * 128 + k0 + c4];
            Bh[n][c4 + 0] = f2tf32(wv.x);
            Bh[n][c4 + 1] = f2tf32(wv.y);
            Bh[n][c4 + 2] = f2tf32(wv.z);
            Bh[n][c4 + 3] = f2tf32(wv.w);
        }
#pragma unroll
        for (int i = 0; i < 4; i++) {
            int idx = tid + i * 256;
            int r = idx >> 3;
            int c4 = (idx & 7) * 4;
            float4 av = make_float4(0.f, 0.f, 0.f, 0.f);
            if (bm + r < M) av = *(const float4*)&A[(size_t)(bm + r) * 128 + k0 + c4];
            As[r][c4 + 0] = f2tf32(av.x);
            As[r][c4 + 1] = f2tf32(av.y);
            As[r][c4 + 2] = f2tf32(av.z);
            As[r][c4 + 3] = f2tf32(av.w);
        }
        __syncthreads();

#pragma unroll
        for (int kk = 0; kk < 32; kk += 4) {
            unsigned a0[2], a1[2], bh[4];
#pragma unroll
            for (int mt = 0; mt < 2; mt++) {
                int row = wm + mt * 16 + lr;
                a0[mt] = As[row][kk + lc];
                a1[mt] = As[row + 8][kk + lc];
            }
#pragma unroll
            for (int nt = 0; nt < 4; nt++) {
                int n = wn + nt * 8 + lr;
                bh[nt] = Bh[n][kk + lc];
            }
#pragma unroll
            for (int mt = 0; mt < 2; mt++)
#pragma unroll
                for (int nt = 0; nt < 4; nt++)
                    mma_k4(c[mt][nt], a0[mt], a1[mt], bh[nt]);
        }
        __syncthreads();
    }

#pragma unroll
    for (int mt = 0; mt < 2; mt++) {
#pragma unroll
        for (int nt = 0; nt < 4; nt++) {
            int r0 = bm + wm + mt * 16 + lr;
            int cc = bn + wn + nt * 8 + lc * 2;
            float b0v = bias[cc], b1v = bias[cc + 1];
            if (r0 < M) {
                C[(size_t)r0 * Ncol + cc]     = c[mt][nt][0] + b0v;
                C[(size_t)r0 * Ncol + cc + 1] = c[mt][nt][1] + b1v;
            }
            if (r0 + 8 < M) {
                C[(size_t)(r0 + 8) * Ncol + cc]     = c[mt][nt][2] + b0v;
                C[(size_t)(r0 + 8) * Ncol + cc + 1] = c[mt][nt][3] + b1v;
            }
        }
    }
}

// ---------------- GATv2 layer 1: warp/node; lane owns 4 channels -----------
// head = lane>>3 (8 lanes per head); score reduce = 3-step 8-lane butterfly.
__global__ void k_gat1(const float* __restrict__ We, const float* __restrict__ att,
                       const float* __restrict__ bias) {
    int gw = (blockIdx.x * blockDim.x + threadIdx.x) >> 5;
    int lane = threadIdx.x & 31;
    if (gw >= NN) return;
    int v = gw;
    int cb = 4 * lane;                   // first channel this lane owns
    float4 a4 = *(const float4*)&att[cb];
    float w0[4], w1[4], w2[4];
#pragma unroll
    for (int j = 0; j < 4; j++) {
        w0[j] = We[(cb + j) * 3 + 0];
        w1[j] = We[(cb + j) * 3 + 1];
        w2[j] = We[(cb + j) * 3 + 2];
    }
    float4 xr = *(const float4*)&g_xr1[(long)v * 128 + cb];
    float mx = -1e30f, den = 0.f;
    float4 acc = make_float4(0.f, 0.f, 0.f, 0.f);
    int pbeg = g_rowptr[v], pend = g_rowptr[v + 1];
    float se0 = 0.f, se1 = 0.f, se2 = 0.f;
#pragma unroll 2
    for (int p = pbeg; p < pend; ++p) {
        float4 q = g_edge[p];
        int s = __float_as_int(q.w);
        se0 += q.x; se1 += q.y; se2 += q.z;
        float4 xl = *(const float4*)&g_xl1[(long)s * 128 + cb];
        float m0 = xl.x + xr.x + w0[0] * q.x + w1[0] * q.y + w2[0] * q.z;
        float m1 = xl.y + xr.y + w0[1] * q.x + w1[1] * q.y + w2[1] * q.z;
        float m2 = xl.z + xr.z + w0[2] * q.x + w1[2] * q.y + w2[2] * q.z;
        float m3 = xl.w + xr.w + w0[3] * q.x + w1[3] * q.y + w2[3] * q.z;
        m0 = (m0 > 0.f) ? m0 : 0.2f * m0;
        m1 = (m1 > 0.f) ? m1 : 0.2f * m1;
        m2 = (m2 > 0.f) ? m2 : 0.2f * m2;
        m3 = (m3 > 0.f) ? m3 : 0.2f * m3;
        float part = m0 * a4.x + m1 * a4.y + m2 * a4.z + m3 * a4.w;
        part += __shfl_xor_sync(0xffffffffu, part, 1);
        part += __shfl_xor_sync(0xffffffffu, part, 2);
        part += __shfl_xor_sync(0xffffffffu, part, 4);   // head score (8-lane group)
        float nm = fmaxf(mx, part);
        float corr = __expf(mx - nm);
        float pe = __expf(part - nm);
        den = den * corr + pe;
        acc.x = acc.x * corr + pe * xl.x;
        acc.y = acc.y * corr + pe * xl.y;
        acc.z = acc.z * corr + pe * xl.z;
        acc.w = acc.w * corr + pe * xl.w;
        mx = nm;
    }
    // self-loop: attr = mean of incoming real-edge attrs, src = v
    {
        float cinv = 1.f / fmaxf((float)(pend - pbeg), 1.f);
        float e0 = se0 * cinv, e1 = se1 * cinv, e2 = se2 * cinv;
        float4 xl = *(const float4*)&g_xl1[(long)v * 128 + cb];
        float m0 = xl.x + xr.x + w0[0] * e0 + w1[0] * e1 + w2[0] * e2;
        float m1 = xl.y + xr.y + w0[1] * e0 + w1[1] * e1 + w2[1] * e2;
        float m2 = xl.z + xr.z + w0[2] * e0 + w1[2] * e1 + w2[2] * e2;
        float m3 = xl.w + xr.w + w0[3] * e0 + w1[3] * e1 + w2[3] * e2;
        m0 = (m0 > 0.f) ? m0 : 0.2f * m0;
        m1 = (m1 > 0.f) ? m1 : 0.2f * m1;
        m2 = (m2 > 0.f) ? m2 : 0.2f * m2;
        m3 = (m3 > 0.f) ? m3 : 0.2f * m3;
        float part = m0 * a4.x + m1 * a4.y + m2 * a4.z + m3 * a4.w;
        part += __shfl_xor_sync(0xffffffffu, part, 1);
        part += __shfl_xor_sync(0xffffffffu, part, 2);
        part += __shfl_xor_sync(0xffffffffu, part, 4);
        float nm = fmaxf(mx, part);
        float corr = __expf(mx - nm);
        float pe = __expf(part - nm);
        den = den * corr + pe;
        acc.x = acc.x * corr + pe * xl.x;
        acc.y = acc.y * corr + pe * xl.y;
        acc.z = acc.z * corr + pe * xl.z;
        acc.w = acc.w * corr + pe * xl.w;
    }
    float4 b4 = *(const float4*)&bias[cb];
    float inv = 1.f / den;
    float4 o;
    o.x = acc.x * inv + b4.x;
    o.y = acc.y * inv + b4.y;
    o.z = acc.z * inv + b4.z;
    o.w = acc.w * inv + b4.w;
    o.x = (o.x > 0.f) ? o.x : (__expf(o.x) - 1.f);
    o.y = (o.y > 0.f) ? o.y : (__expf(o.y) - 1.f);
    o.z = (o.z > 0.f) ? o.z : (__expf(o.z) - 1.f);
    o.w = (o.w > 0.f) ? o.w : (__expf(o.w) - 1.f);
    *(float4*)&g_h1[(long)v * 128 + cb] = o;
}

// ---------------- GATv2 layer 2 + fused mean pooling; lane owns 2 channels --
__global__ void k_gat2(const float* __restrict__ We, const float* __restrict__ att,
                       const float* __restrict__ bias, const int* __restrict__ batch) {
    int gw = (blockIdx.x * blockDim.x + threadIdx.x) >> 5;
    int lane = threadIdx.x & 31;
    if (gw >= NN) return;
    int v = gw;
    int c0 = 2 * lane, c1 = 2 * lane + 1;
    float aa = att[c0], ab = att[c1];
    float wa0 = We[c0 * 3 + 0], wa1 = We[c0 * 3 + 1], wa2 = We[c0 * 3 + 2];
    float wb0 = We[c1 * 3 + 0], wb1 = We[c1 * 3 + 1], wb2 = We[c1 * 3 + 2];
    float2 xr = *(const float2*)&g_xr2[(long)v * 64 + c0];
    float mx = -1e30f, den = 0.f, acca = 0.f, accb = 0.f;
    int pbeg = g_rowptr[v], pend = g_rowptr[v + 1];
    float se0 = 0.f, se1 = 0.f, se2 = 0.f;
#pragma unroll 2
    for (int p = pbeg; p < pend; ++p) {
        float4 q = g_edge[p];
        int s = __float_as_int(q.w);
        se0 += q.x; se1 += q.y; se2 += q.z;
        float2 xl = *(const float2*)&g_xl2[(long)s * 64 + c0];
        float ma = xl.x + xr.x + wa0 * q.x + wa1 * q.y + wa2 * q.z;
        float mb = xl.y + xr.y + wb0 * q.x + wb1 * q.y + wb2 * q.z;
        ma = (ma > 0.f) ? ma : 0.2f * ma;
        mb = (mb > 0.f) ? mb : 0.2f * mb;
        float sc = ma * aa + mb * ab;
#pragma unroll
        for (int off = 16; off > 0; off >>= 1)
            sc += __shfl_xor_sync(0xffffffffu, sc, off);
        float nm = fmaxf(mx, sc);
        float corr = __expf(mx - nm);
        float pe = __expf(sc - nm);
        den = den * corr + pe;
        acca = acca * corr + pe * xl.x;
        accb = accb * corr + pe * xl.y;
        mx = nm;
    }
    // self-loop
    {
        float cinv = 1.f / fmaxf((float)(pend - pbeg), 1.f);
        float e0 = se0 * cinv, e1 = se1 * cinv, e2 = se2 * cinv;
        float2 xl = *(const float2*)&g_xl2[(long)v * 64 + c0];
        float ma = xl.x + xr.x + wa0 * e0 + wa1 * e1 + wa2 * e2;
        float mb = xl.y + xr.y + wb0 * e0 + wb1 * e1 + wb2 * e2;
        ma = (ma > 0.f) ? ma : 0.2f * ma;
        mb = (mb > 0.f) ? mb : 0.2f * mb;
        float sc = ma * aa + mb * ab;
#pragma unroll
        for (int off = 16; off > 0; off >>= 1)
            sc += __shfl_xor_sync(0xffffffffu, sc, off);
        float nm = fmaxf(mx, sc);
        float corr = __expf(mx - nm);
        float pe = __expf(sc - nm);
        den = den * corr + pe;
        acca = acca * corr + pe * xl.x;
        accb = accb * corr + pe * xl.y;
    }
    float oa = acca / den + bias[c0];
    float ob = accb / den + bias[c1];
    oa = (oa > 0.f) ? oa : (__expf(oa) - 1.f);
    ob = (ob > 0.f) ? ob : (__expf(ob) - 1.f);
    int b = batch[v];
    atomicAdd(&g_pooled[b * 64 + c0], oa);
    atomicAdd(&g_pooled[b * 64 + c1], ob);
    if (lane == 0) atomicAdd(&g_gcnt[b], 1);
}

// ---------------- head MLP: block per graph --------------------------------
__global__ void k_head(const float* __restrict__ u,
                       const float* __restrict__ Wl, const float* __restrict__ bl,
                       const float* __restrict__ Wh, const float* __restrict__ bh,
                       float* __restrict__ out) {
    int g = blockIdx.x;
    __shared__ float pm[64];
    __shared__ float z[32];
    int t = threadIdx.x;   // 64 threads
    float c = fmaxf((float)g_gcnt[g], 1.f);
    pm[t] = g_pooled[g * 64 + t] / c;
    __syncthreads();
    if (t < 32) {
        float s = bl[t];
#pragma unroll
        for (int k = 0; k < 64; k++) s += pm[k] * Wl[t * 65 + k];
        s += u[g] * Wl[t * 65 + 64];
        z[t] = fmaxf(s, 0.f);
    }
    __syncthreads();
    if (t < 10) {
        float s = bh[t];
#pragma unroll
        for (int j = 0; j < 32; j++) s += z[j] * Wh[t * 32 + j];
        out[g * 10 + t] = s;
    }
}

// ---------------- launch ----------------------------------------------------
extern "C" void kernel_launch(void* const* d_in, const int* in_sizes, int n_in,
                              void* d_out, int out_size) {
    const float* x     = (const float*)d_in[0];
    const int*   ei    = (const int*)d_in[1];
    const float* ea    = (const float*)d_in[2];
    const int*   batch = (const int*)d_in[3];
    const float* u     = (const float*)d_in[4];
    const float* Wl1   = (const float*)d_in[5];
    const float* bl1   = (const float*)d_in[6];
    const float* Wr1   = (const float*)d_in[7];
    const float* br1   = (const float*)d_in[8];
    const float* We1   = (const float*)d_in[9];
    const float* att1  = (const float*)d_in[10];
    const float* b1    = (const float*)d_in[11];
    const float* Wl2   = (const float*)d_in[12];
    const float* bl2   = (const float*)d_in[13];
    const float* Wr2   = (const float*)d_in[14];
    const float* br2   = (const float*)d_in[15];
    const float* We2   = (const float*)d_in[16];
    const float* att2  = (const float*)d_in[17];
    const float* b2    = (const float*)d_in[18];
    const float* Wlin  = (const float*)d_in[19];
    const float* blin  = (const float*)d_in[20];
    const float* Wh    = (const float*)d_in[21];
    const float* bh    = (const float*)d_in[22];
    float* out = (float*)d_out;

    float *p_xl1, *p_xr1, *p_h1, *p_xl2, *p_xr2;
    cudaGetSymbolAddress((void**)&p_xl1, g_xl1);
    cudaGetSymbolAddress((void**)&p_xr1, g_xr1);
    cudaGetSymbolAddress((void**)&p_h1,  g_h1);
    cudaGetSymbolAddress((void**)&p_xl2, g_xl2);
    cudaGetSymbolAddress((void**)&p_xr2, g_xr2);

    // fork: GEMM1 (needs only x) runs concurrently with the CSR build
    cudaStream_t side;
    cudaStreamCreateWithFlags(&side, cudaStreamNonBlocking);
    cudaEvent_t evFork, evJoin;
    cudaEventCreateWithFlags(&evFork, cudaEventDisableTiming);
    cudaEventCreateWithFlags(&evJoin, cudaEventDisableTiming);

    cudaEventRecord(evFork, 0);
    cudaStreamWaitEvent(side, evFork, 0);
    dim3 g1(2, (NN + 127) / 128, 2);
    gemm_tf32<<<g1, 256, 0, side>>>(x, Wl1, Wr1, bl1, br1, p_xl1, p_xr1, NN, 128);
    cudaEventRecord(evJoin, side);

    k_zero<<<(NN + 255) / 256, 256>>>();            // covers NN (> GG*64)
    k_degree<<<(EE + 255) / 256, 256>>>(ei);
    k_scan1<<<64, 256>>>();
    k_scan3<<<64, 256>>>();
    k_scatter<<<(EE + 255) / 256, 256>>>(ei, ea);

    cudaStreamWaitEvent(0, evJoin, 0);
    k_gat1<<<(NN + 7) / 8, 256>>>(We1, att1, b1);

    dim3 g2(1, (NN + 127) / 128, 2);
    gemm_tf32<<<g2, 256>>>(p_h1, Wl2, Wr2, bl2, br2, p_xl2, p_xr2, NN, 64);

    k_gat2<<<(NN + 7) / 8, 256>>>(We2, att2, b2, batch);

    k_head<<<GG, 64>>>(u, Wlin, blin, Wh, bh, out);

    cudaEventDestroy(evFork);
    cudaEventDestroy(evJoin);
    cudaStreamDestroy(side);
}